// round 6
// baseline (speedup 1.0000x reference)
#include <cuda_runtime.h>
#include <cuda_fp16.h>
#include <math.h>
#include <stdint.h>

#define N_NODES 100000
#define N_EDGES 1600000
#define D 128
#define NEG_SLOPE 0.01f
#define SCAN_BLKS ((N_NODES + 1023) / 1024)   // 98

typedef unsigned long long u64;

// ---------------- scratch (no allocations allowed) ----------------
__device__ __half2 g_zh[N_NODES * (D / 2)];   // 25.6 MB, z in fp16
__device__ float g_ssrc[N_NODES];
__device__ float g_sdst[N_NODES];
__device__ int   g_deg[N_NODES];
__device__ int   g_off[N_NODES + 1];
__device__ int   g_cur[N_NODES];
__device__ int2  g_csr_sw[N_EDGES];           // packed (src, weight-bits)
__device__ int   g_bsum[128];
__device__ int   g_boff[128];

// ---------------- f32x2 helpers ----------------
__device__ __forceinline__ u64 ffma2(u64 a, u64 b, u64 c) {
    u64 d;
    asm("fma.rn.f32x2 %0, %1, %2, %3;" : "=l"(d) : "l"(a), "l"(b), "l"(c));
    return d;
}
__device__ __forceinline__ float2 u2f(u64 v) {
    float2 f;
    asm("mov.b64 {%0, %1}, %2;" : "=f"(f.x), "=f"(f.y) : "l"(v));
    return f;
}

// ---------------- GEMM z = h@W with fused scores, f32x2 math ----------------
// BM=128, full N=128, BK=16. 256 threads, 8x8 per thread via 32 FFMA2/k.
#define GBM 128
#define GBK 16
// smem: hTd[16][128] float2 (duplicated pairs, 16KB) + wS[16][128] float (8KB)
#define SMEM_FLOATS (GBK * 256 + GBK * 128)

__global__ __launch_bounds__(256) void gemm_scores_kernel(const float* __restrict__ h,
                                                          const float* __restrict__ W,
                                                          const float* __restrict__ attn) {
    __shared__ __align__(16) float smem[SMEM_FLOATS];
    float2* hTd = reinterpret_cast<float2*>(smem);      // [GBK][128] float2, (a,a)
    float*  wS  = smem + GBK * 256;                     // [GBK][128]
    float*  sp1 = smem;                                 // [128][17] (reused)
    float*  sp2 = smem + 128 * 17;

    const int t  = threadIdx.x;
    const int tx = t & 15;
    const int ty = t >> 4;
    const int row0 = blockIdx.x * GBM;

    u64 acc2[8][4];
    #pragma unroll
    for (int i = 0; i < 8; i++)
        #pragma unroll
        for (int jp = 0; jp < 4; jp++) acc2[i][jp] = 0ull;

    for (int k0 = 0; k0 < D; k0 += GBK) {
        // load h tile [128 rows][16 k], transpose + duplicate into hTd[k][r]=(a,a)
        #pragma unroll
        for (int q = t; q < 512; q += 256) {
            int r  = q >> 2;
            int c4 = (q & 3) << 2;
            int grow = row0 + r;
            float4 v = make_float4(0.f, 0.f, 0.f, 0.f);
            if (grow < N_NODES)
                v = *reinterpret_cast<const float4*>(&h[grow * D + k0 + c4]);
            hTd[(c4 + 0) * 128 + r] = make_float2(v.x, v.x);
            hTd[(c4 + 1) * 128 + r] = make_float2(v.y, v.y);
            hTd[(c4 + 2) * 128 + r] = make_float2(v.z, v.z);
            hTd[(c4 + 3) * 128 + r] = make_float2(v.w, v.w);
        }
        // load W tile [16][128]
        #pragma unroll
        for (int q = t; q < 512; q += 256) {
            int r = q >> 5;
            int c = (q & 31) << 2;
            *reinterpret_cast<float4*>(&wS[r * D + c]) =
                *reinterpret_cast<const float4*>(&W[(k0 + r) * D + c]);
        }
        __syncthreads();

        #pragma unroll
        for (int kk = 0; kk < GBK; kk++) {
            const ulonglong2* aP =
                reinterpret_cast<const ulonglong2*>(&hTd[kk * 128 + ty * 8]);
            ulonglong2 A0 = aP[0];   // (a0,a0),(a1,a1)
            ulonglong2 A1 = aP[1];
            ulonglong2 A2 = aP[2];
            ulonglong2 A3 = aP[3];
            const ulonglong2* bP =
                reinterpret_cast<const ulonglong2*>(&wS[kk * D + tx * 8]);
            ulonglong2 B0 = bP[0];   // (b0,b1),(b2,b3)
            ulonglong2 B1 = bP[1];   // (b4,b5),(b6,b7)
            u64 ad[8] = {A0.x, A0.y, A1.x, A1.y, A2.x, A2.y, A3.x, A3.y};
            u64 bd[4] = {B0.x, B0.y, B1.x, B1.y};
            #pragma unroll
            for (int i = 0; i < 8; i++)
                #pragma unroll
                for (int jp = 0; jp < 4; jp++)
                    acc2[i][jp] = ffma2(ad[i], bd[jp], acc2[i][jp]);
        }
        __syncthreads();
    }

    // write z as fp16
    #pragma unroll
    for (int i = 0; i < 8; i++) {
        int grow = row0 + ty * 8 + i;
        if (grow < N_NODES) {
            __half2 hv[4];
            #pragma unroll
            for (int jp = 0; jp < 4; jp++) {
                float2 f = u2f(acc2[i][jp]);
                hv[jp] = __floats2half2_rn(f.x, f.y);
            }
            *reinterpret_cast<uint4*>(&g_zh[grow * (D / 2) + tx * 4]) =
                *reinterpret_cast<uint4*>(hv);
        }
    }

    // fused scores (fp32)
    float a1v[8], a2v[8];
    #pragma unroll
    for (int j = 0; j < 8; j++) {
        a1v[j] = attn[tx * 8 + j];
        a2v[j] = attn[D + tx * 8 + j];
    }
    float p1r[8], p2r[8];
    #pragma unroll
    for (int i = 0; i < 8; i++) {
        float p1 = 0.f, p2 = 0.f;
        #pragma unroll
        for (int jp = 0; jp < 4; jp++) {
            float2 f = u2f(acc2[i][jp]);
            p1 += f.x * a1v[2 * jp] + f.y * a1v[2 * jp + 1];
            p2 += f.x * a2v[2 * jp] + f.y * a2v[2 * jp + 1];
        }
        p1r[i] = p1; p2r[i] = p2;
    }
    __syncthreads();   // smem reuse barrier
    #pragma unroll
    for (int i = 0; i < 8; i++) {
        sp1[(ty * 8 + i) * 17 + tx] = p1r[i];
        sp2[(ty * 8 + i) * 17 + tx] = p2r[i];
    }
    __syncthreads();
    if (t < 128) {
        int grow = row0 + t;
        if (grow < N_NODES) {
            float s1 = 0.f, s2 = 0.f;
            #pragma unroll
            for (int k = 0; k < 16; k++) {
                s1 += sp1[t * 17 + k];
                s2 += sp2[t * 17 + k];
            }
            g_ssrc[grow] = s1;
            g_sdst[grow] = s2;
        }
    }
}

// ---------------- CSR build ----------------
__global__ void zero_deg_kernel() {
    int i = blockIdx.x * blockDim.x + threadIdx.x;
    if (i < N_NODES) g_deg[i] = 0;
}

// 4 edges per thread for MLP
__global__ void hist_kernel(const int* __restrict__ dst) {
    int i = blockIdx.x * blockDim.x + threadIdx.x;
    int base = i * 4;
    if (base + 3 < N_EDGES) {
        int4 v = *reinterpret_cast<const int4*>(&dst[base]);
        atomicAdd(&g_deg[v.x], 1);
        atomicAdd(&g_deg[v.y], 1);
        atomicAdd(&g_deg[v.z], 1);
        atomicAdd(&g_deg[v.w], 1);
    } else {
        for (int k = base; k < N_EDGES; k++) atomicAdd(&g_deg[dst[k]], 1);
    }
}

__global__ __launch_bounds__(1024) void scan1_kernel() {
    __shared__ int wsum[32];
    int t = threadIdx.x, lane = t & 31, wid = t >> 5;
    int i = blockIdx.x * 1024 + t;
    int v = (i < N_NODES) ? g_deg[i] : 0;
    int x = v;
    #pragma unroll
    for (int o = 1; o < 32; o <<= 1) {
        int y = __shfl_up_sync(0xffffffffu, x, o);
        if (lane >= o) x += y;
    }
    if (lane == 31) wsum[wid] = x;
    __syncthreads();
    if (wid == 0) {
        int s = wsum[lane];
        #pragma unroll
        for (int o = 1; o < 32; o <<= 1) {
            int y = __shfl_up_sync(0xffffffffu, s, o);
            if (lane >= o) s += y;
        }
        wsum[lane] = s;
    }
    __syncthreads();
    int prefix = (wid > 0) ? wsum[wid - 1] : 0;
    int incl = x + prefix;
    if (i < N_NODES) g_off[i] = incl - v;
    if (t == 1023) g_bsum[blockIdx.x] = incl;
}

__global__ __launch_bounds__(128) void scan2_kernel() {
    __shared__ int wsum[4];
    int t = threadIdx.x, lane = t & 31, wid = t >> 5;
    int v = (t < SCAN_BLKS) ? g_bsum[t] : 0;
    int x = v;
    #pragma unroll
    for (int o = 1; o < 32; o <<= 1) {
        int y = __shfl_up_sync(0xffffffffu, x, o);
        if (lane >= o) x += y;
    }
    if (lane == 31) wsum[wid] = x;
    __syncthreads();
    int prefix = 0;
    for (int k = 0; k < wid; k++) prefix += wsum[k];
    int incl = x + prefix;
    if (t < SCAN_BLKS) g_boff[t] = incl - v;
}

__global__ void scan3_kernel() {
    int i = blockIdx.x * blockDim.x + threadIdx.x;
    if (i < N_NODES) {
        int v = g_off[i] + g_boff[i >> 10];
        g_off[i] = v;
        g_cur[i] = v;
    }
    if (i == 0) g_off[N_NODES] = N_EDGES;
}

// scatter + weight precompute: store packed (src, expf(leaky(s))) per CSR slot
__global__ void scatter_kernel(const int* __restrict__ src, const int* __restrict__ dst) {
    int i = blockIdx.x * blockDim.x + threadIdx.x;
    int base = i * 2;
    if (base + 1 < N_EDGES) {
        int2 sv = *reinterpret_cast<const int2*>(&src[base]);
        int2 dv = *reinterpret_cast<const int2*>(&dst[base]);
        {
            float e = g_ssrc[sv.x] + g_sdst[dv.x];
            e = (e > 0.f) ? e : NEG_SLOPE * e;
            float w = __expf(e);
            int p = atomicAdd(&g_cur[dv.x], 1);
            g_csr_sw[p] = make_int2(sv.x, __float_as_int(w));
        }
        {
            float e = g_ssrc[sv.y] + g_sdst[dv.y];
            e = (e > 0.f) ? e : NEG_SLOPE * e;
            float w = __expf(e);
            int p = atomicAdd(&g_cur[dv.y], 1);
            g_csr_sw[p] = make_int2(sv.y, __float_as_int(w));
        }
    } else if (base < N_EDGES) {
        int s = src[base], d0 = dst[base];
        float e = g_ssrc[s] + g_sdst[d0];
        e = (e > 0.f) ? e : NEG_SLOPE * e;
        float w = __expf(e);
        int p = atomicAdd(&g_cur[d0], 1);
        g_csr_sw[p] = make_int2(s, __float_as_int(w));
    }
}

// ---------------- single-pass aggregation (precomputed weights) ----------------
// out_n = (sum_j w_j z_j) / (sum_j w_j); one warp per node; lane owns 4 cols.
__global__ __launch_bounds__(256) void aggregate_kernel(float* __restrict__ out) {
    int wid  = threadIdx.x >> 5;
    int lane = threadIdx.x & 31;
    int n    = blockIdx.x * 8 + wid;
    if (n >= N_NODES) return;

    int start = g_off[n];
    int end   = g_off[n + 1];

    const uint2* __restrict__ z2 = reinterpret_cast<const uint2*>(g_zh);
    float4 acc = make_float4(0.f, 0.f, 0.f, 0.f);
    float den_l = 0.f;

    for (int base = start; base < end; base += 32) {
        int cnt = end - base;
        if (cnt > 32) cnt = 32;
        int2 sw = make_int2(0, 0);
        if (lane < cnt) sw = g_csr_sw[base + lane];
        den_l += __int_as_float(sw.y);

        int j = 0;
        for (; j + 4 <= cnt; j += 4) {
            int s0 = __shfl_sync(0xffffffffu, sw.x, j);
            int s1 = __shfl_sync(0xffffffffu, sw.x, j + 1);
            int s2 = __shfl_sync(0xffffffffu, sw.x, j + 2);
            int s3 = __shfl_sync(0xffffffffu, sw.x, j + 3);
            float w0 = __int_as_float(__shfl_sync(0xffffffffu, sw.y, j));
            float w1 = __int_as_float(__shfl_sync(0xffffffffu, sw.y, j + 1));
            float w2 = __int_as_float(__shfl_sync(0xffffffffu, sw.y, j + 2));
            float w3 = __int_as_float(__shfl_sync(0xffffffffu, sw.y, j + 3));
            uint2 r0 = z2[s0 * 32 + lane];
            uint2 r1 = z2[s1 * 32 + lane];
            uint2 r2 = z2[s2 * 32 + lane];
            uint2 r3 = z2[s3 * 32 + lane];
            float2 a0 = __half22float2(*reinterpret_cast<__half2*>(&r0.x));
            float2 b0 = __half22float2(*reinterpret_cast<__half2*>(&r0.y));
            float2 a1 = __half22float2(*reinterpret_cast<__half2*>(&r1.x));
            float2 b1 = __half22float2(*reinterpret_cast<__half2*>(&r1.y));
            float2 a2 = __half22float2(*reinterpret_cast<__half2*>(&r2.x));
            float2 b2 = __half22float2(*reinterpret_cast<__half2*>(&r2.y));
            float2 a3 = __half22float2(*reinterpret_cast<__half2*>(&r3.x));
            float2 b3 = __half22float2(*reinterpret_cast<__half2*>(&r3.y));
            acc.x += w0 * a0.x; acc.y += w0 * a0.y; acc.z += w0 * b0.x; acc.w += w0 * b0.y;
            acc.x += w1 * a1.x; acc.y += w1 * a1.y; acc.z += w1 * b1.x; acc.w += w1 * b1.y;
            acc.x += w2 * a2.x; acc.y += w2 * a2.y; acc.z += w2 * b2.x; acc.w += w2 * b2.y;
            acc.x += w3 * a3.x; acc.y += w3 * a3.y; acc.z += w3 * b3.x; acc.w += w3 * b3.y;
        }
        for (; j < cnt; j++) {
            int   sj = __shfl_sync(0xffffffffu, sw.x, j);
            float wj = __int_as_float(__shfl_sync(0xffffffffu, sw.y, j));
            uint2 r = z2[sj * 32 + lane];
            float2 za = __half22float2(*reinterpret_cast<__half2*>(&r.x));
            float2 zb = __half22float2(*reinterpret_cast<__half2*>(&r.y));
            acc.x += wj * za.x; acc.y += wj * za.y;
            acc.z += wj * zb.x; acc.w += wj * zb.y;
        }
    }
    #pragma unroll
    for (int o = 16; o > 0; o >>= 1)
        den_l += __shfl_xor_sync(0xffffffffu, den_l, o);

    float inv = (end > start) ? (1.0f / den_l) : 0.f;
    acc.x *= inv; acc.y *= inv; acc.z *= inv; acc.w *= inv;
    *reinterpret_cast<float4*>(&out[n * D + lane * 4]) = acc;
}

// ---------------- launch ----------------
extern "C" void kernel_launch(void* const* d_in, const int* in_sizes, int n_in,
                              void* d_out, int out_size) {
    const float* h    = (const float*)d_in[0];
    const float* W    = (const float*)d_in[1];
    const float* attn = (const float*)d_in[2];
    const int* esrc   = (const int*)d_in[3];
    const int* edst   = (const int*)d_in[4];
    float* out        = (float*)d_out;

    (void)in_sizes; (void)n_in; (void)out_size;

    gemm_scores_kernel<<<(N_NODES + GBM - 1) / GBM, 256>>>(h, W, attn);
    zero_deg_kernel<<<(N_NODES + 255) / 256, 256>>>();
    hist_kernel<<<(N_EDGES / 4 + 255) / 256, 256>>>(edst);
    scan1_kernel<<<SCAN_BLKS, 1024>>>();
    scan2_kernel<<<1, 128>>>();
    scan3_kernel<<<(N_NODES + 255) / 256, 256>>>();
    scatter_kernel<<<(N_EDGES / 2 + 255) / 256, 256>>>(esrc, edst);
    aggregate_kernel<<<(N_NODES + 7) / 8, 256>>>(out);
}

// round 7
// speedup vs baseline: 1.0777x; 1.0777x over previous
#include <cuda_runtime.h>
#include <cuda_fp16.h>
#include <math.h>
#include <stdint.h>

#define N_NODES 100000
#define N_EDGES 1600000
#define D 128
#define NEG_SLOPE 0.01f
#define SCAN_BLKS ((N_NODES + 1023) / 1024)   // 98

// ---------------- scratch (no allocations allowed) ----------------
__device__ __half2 g_zh[N_NODES * (D / 2)];   // 25.6 MB, z in fp16
__device__ float g_ssrc[N_NODES];
__device__ float g_sdst[N_NODES];
__device__ int   g_deg[N_NODES];
__device__ int   g_off[N_NODES + 1];
__device__ int   g_cur[N_NODES];
__device__ int2  g_csr_sw[N_EDGES];           // packed (src, weight-bits)
__device__ int   g_bsum[128];
__device__ int   g_boff[128];

// ---------------- GEMM z = h@W with fused scores (scalar FFMA, round-5 proven) ----------------
#define GBM 128
#define GBK 16
#define HT_STRIDE 132
#define SMEM_FLOATS 4352

__global__ __launch_bounds__(256) void gemm_scores_kernel(const float* __restrict__ h,
                                                          const float* __restrict__ W,
                                                          const float* __restrict__ attn) {
    __shared__ float smem[SMEM_FLOATS];
    float* hT = smem;                       // [GBK][HT_STRIDE]
    float* wS = smem + GBK * HT_STRIDE;     // [GBK][128]
    float* sp1 = smem;                      // [128][17] (reused)
    float* sp2 = smem + 128 * 17;

    const int t  = threadIdx.x;
    const int tx = t & 15;
    const int ty = t >> 4;
    const int row0 = blockIdx.x * GBM;

    float acc[8][8];
    #pragma unroll
    for (int i = 0; i < 8; i++)
        #pragma unroll
        for (int j = 0; j < 8; j++) acc[i][j] = 0.0f;

    for (int k0 = 0; k0 < D; k0 += GBK) {
        #pragma unroll
        for (int q = t; q < 512; q += 256) {
            int r  = q >> 2;
            int c4 = (q & 3) << 2;
            int grow = row0 + r;
            float4 v = make_float4(0.f, 0.f, 0.f, 0.f);
            if (grow < N_NODES)
                v = *reinterpret_cast<const float4*>(&h[grow * D + k0 + c4]);
            hT[(c4 + 0) * HT_STRIDE + r] = v.x;
            hT[(c4 + 1) * HT_STRIDE + r] = v.y;
            hT[(c4 + 2) * HT_STRIDE + r] = v.z;
            hT[(c4 + 3) * HT_STRIDE + r] = v.w;
        }
        #pragma unroll
        for (int q = t; q < 512; q += 256) {
            int r = q >> 5;
            int c = (q & 31) << 2;
            *reinterpret_cast<float4*>(&wS[r * D + c]) =
                *reinterpret_cast<const float4*>(&W[(k0 + r) * D + c]);
        }
        __syncthreads();

        #pragma unroll
        for (int kk = 0; kk < GBK; kk++) {
            float4 a0 = *reinterpret_cast<const float4*>(&hT[kk * HT_STRIDE + ty * 8]);
            float4 a1 = *reinterpret_cast<const float4*>(&hT[kk * HT_STRIDE + ty * 8 + 4]);
            float4 b0 = *reinterpret_cast<const float4*>(&wS[kk * D + tx * 8]);
            float4 b1 = *reinterpret_cast<const float4*>(&wS[kk * D + tx * 8 + 4]);
            float av[8] = {a0.x, a0.y, a0.z, a0.w, a1.x, a1.y, a1.z, a1.w};
            float bv[8] = {b0.x, b0.y, b0.z, b0.w, b1.x, b1.y, b1.z, b1.w};
            #pragma unroll
            for (int i = 0; i < 8; i++)
                #pragma unroll
                for (int j = 0; j < 8; j++)
                    acc[i][j] += av[i] * bv[j];
        }
        __syncthreads();
    }

    // write z as fp16
    #pragma unroll
    for (int i = 0; i < 8; i++) {
        int grow = row0 + ty * 8 + i;
        if (grow < N_NODES) {
            __half2 hv[4];
            #pragma unroll
            for (int j = 0; j < 4; j++)
                hv[j] = __floats2half2_rn(acc[i][2 * j], acc[i][2 * j + 1]);
            *reinterpret_cast<uint4*>(&g_zh[grow * (D / 2) + tx * 4]) =
                *reinterpret_cast<uint4*>(hv);
        }
    }

    // fused scores (fp32)
    float a1v[8], a2v[8];
    #pragma unroll
    for (int j = 0; j < 8; j++) {
        a1v[j] = attn[tx * 8 + j];
        a2v[j] = attn[D + tx * 8 + j];
    }
    float p1r[8], p2r[8];
    #pragma unroll
    for (int i = 0; i < 8; i++) {
        float p1 = 0.f, p2 = 0.f;
        #pragma unroll
        for (int j = 0; j < 8; j++) {
            p1 += acc[i][j] * a1v[j];
            p2 += acc[i][j] * a2v[j];
        }
        p1r[i] = p1; p2r[i] = p2;
    }
    __syncthreads();
    #pragma unroll
    for (int i = 0; i < 8; i++) {
        sp1[(ty * 8 + i) * 17 + tx] = p1r[i];
        sp2[(ty * 8 + i) * 17 + tx] = p2r[i];
    }
    __syncthreads();
    if (t < 128) {
        int grow = row0 + t;
        if (grow < N_NODES) {
            float s1 = 0.f, s2 = 0.f;
            #pragma unroll
            for (int k = 0; k < 16; k++) {
                s1 += sp1[t * 17 + k];
                s2 += sp2[t * 17 + k];
            }
            g_ssrc[grow] = s1;
            g_sdst[grow] = s2;
        }
    }
}

// ---------------- CSR build ----------------
__global__ void zero_deg_kernel() {
    int i = blockIdx.x * blockDim.x + threadIdx.x;
    if (i < N_NODES) g_deg[i] = 0;
}

// 4 edges per thread for MLP
__global__ void hist_kernel(const int* __restrict__ dst) {
    int i = blockIdx.x * blockDim.x + threadIdx.x;
    int base = i * 4;
    if (base + 3 < N_EDGES) {
        int4 v = *reinterpret_cast<const int4*>(&dst[base]);
        atomicAdd(&g_deg[v.x], 1);
        atomicAdd(&g_deg[v.y], 1);
        atomicAdd(&g_deg[v.z], 1);
        atomicAdd(&g_deg[v.w], 1);
    } else {
        for (int k = base; k < N_EDGES; k++) atomicAdd(&g_deg[dst[k]], 1);
    }
}

__global__ __launch_bounds__(1024) void scan1_kernel() {
    __shared__ int wsum[32];
    int t = threadIdx.x, lane = t & 31, wid = t >> 5;
    int i = blockIdx.x * 1024 + t;
    int v = (i < N_NODES) ? g_deg[i] : 0;
    int x = v;
    #pragma unroll
    for (int o = 1; o < 32; o <<= 1) {
        int y = __shfl_up_sync(0xffffffffu, x, o);
        if (lane >= o) x += y;
    }
    if (lane == 31) wsum[wid] = x;
    __syncthreads();
    if (wid == 0) {
        int s = wsum[lane];
        #pragma unroll
        for (int o = 1; o < 32; o <<= 1) {
            int y = __shfl_up_sync(0xffffffffu, s, o);
            if (lane >= o) s += y;
        }
        wsum[lane] = s;
    }
    __syncthreads();
    int prefix = (wid > 0) ? wsum[wid - 1] : 0;
    int incl = x + prefix;
    if (i < N_NODES) g_off[i] = incl - v;
    if (t == 1023) g_bsum[blockIdx.x] = incl;
}

__global__ __launch_bounds__(128) void scan2_kernel() {
    __shared__ int wsum[4];
    int t = threadIdx.x, lane = t & 31, wid = t >> 5;
    int v = (t < SCAN_BLKS) ? g_bsum[t] : 0;
    int x = v;
    #pragma unroll
    for (int o = 1; o < 32; o <<= 1) {
        int y = __shfl_up_sync(0xffffffffu, x, o);
        if (lane >= o) x += y;
    }
    if (lane == 31) wsum[wid] = x;
    __syncthreads();
    int prefix = 0;
    for (int k = 0; k < wid; k++) prefix += wsum[k];
    int incl = x + prefix;
    if (t < SCAN_BLKS) g_boff[t] = incl - v;
}

__global__ void scan3_kernel() {
    int i = blockIdx.x * blockDim.x + threadIdx.x;
    if (i < N_NODES) {
        int v = g_off[i] + g_boff[i >> 10];
        g_off[i] = v;
        g_cur[i] = v;
    }
    if (i == 0) g_off[N_NODES] = N_EDGES;
}

// scatter + weight precompute: store packed (src, expf(leaky(s))) per CSR slot
__global__ void scatter_kernel(const int* __restrict__ src, const int* __restrict__ dst) {
    int i = blockIdx.x * blockDim.x + threadIdx.x;
    int base = i * 2;
    if (base + 1 < N_EDGES) {
        int2 sv = *reinterpret_cast<const int2*>(&src[base]);
        int2 dv = *reinterpret_cast<const int2*>(&dst[base]);
        {
            float e = g_ssrc[sv.x] + g_sdst[dv.x];
            e = (e > 0.f) ? e : NEG_SLOPE * e;
            float w = __expf(e);
            int p = atomicAdd(&g_cur[dv.x], 1);
            g_csr_sw[p] = make_int2(sv.x, __float_as_int(w));
        }
        {
            float e = g_ssrc[sv.y] + g_sdst[dv.y];
            e = (e > 0.f) ? e : NEG_SLOPE * e;
            float w = __expf(e);
            int p = atomicAdd(&g_cur[dv.y], 1);
            g_csr_sw[p] = make_int2(sv.y, __float_as_int(w));
        }
    } else if (base < N_EDGES) {
        int s = src[base], d0 = dst[base];
        float e = g_ssrc[s] + g_sdst[d0];
        e = (e > 0.f) ? e : NEG_SLOPE * e;
        float w = __expf(e);
        int p = atomicAdd(&g_cur[d0], 1);
        g_csr_sw[p] = make_int2(s, __float_as_int(w));
    }
}

// ---------------- single-pass aggregation (precomputed weights) ----------------
__global__ __launch_bounds__(256) void aggregate_kernel(float* __restrict__ out) {
    int wid  = threadIdx.x >> 5;
    int lane = threadIdx.x & 31;
    int n    = blockIdx.x * 8 + wid;
    if (n >= N_NODES) return;

    int start = g_off[n];
    int end   = g_off[n + 1];

    const uint2* __restrict__ z2 = reinterpret_cast<const uint2*>(g_zh);
    float4 acc = make_float4(0.f, 0.f, 0.f, 0.f);
    float den_l = 0.f;

    for (int base = start; base < end; base += 32) {
        int cnt = end - base;
        if (cnt > 32) cnt = 32;
        int2 sw = make_int2(0, 0);
        if (lane < cnt) sw = g_csr_sw[base + lane];
        den_l += __int_as_float(sw.y);

        int j = 0;
        for (; j + 4 <= cnt; j += 4) {
            int s0 = __shfl_sync(0xffffffffu, sw.x, j);
            int s1 = __shfl_sync(0xffffffffu, sw.x, j + 1);
            int s2 = __shfl_sync(0xffffffffu, sw.x, j + 2);
            int s3 = __shfl_sync(0xffffffffu, sw.x, j + 3);
            float w0 = __int_as_float(__shfl_sync(0xffffffffu, sw.y, j));
            float w1 = __int_as_float(__shfl_sync(0xffffffffu, sw.y, j + 1));
            float w2 = __int_as_float(__shfl_sync(0xffffffffu, sw.y, j + 2));
            float w3 = __int_as_float(__shfl_sync(0xffffffffu, sw.y, j + 3));
            uint2 r0 = z2[s0 * 32 + lane];
            uint2 r1 = z2[s1 * 32 + lane];
            uint2 r2 = z2[s2 * 32 + lane];
            uint2 r3 = z2[s3 * 32 + lane];
            float2 a0 = __half22float2(*reinterpret_cast<__half2*>(&r0.x));
            float2 b0 = __half22float2(*reinterpret_cast<__half2*>(&r0.y));
            float2 a1 = __half22float2(*reinterpret_cast<__half2*>(&r1.x));
            float2 b1 = __half22float2(*reinterpret_cast<__half2*>(&r1.y));
            float2 a2 = __half22float2(*reinterpret_cast<__half2*>(&r2.x));
            float2 b2 = __half22float2(*reinterpret_cast<__half2*>(&r2.y));
            float2 a3 = __half22float2(*reinterpret_cast<__half2*>(&r3.x));
            float2 b3 = __half22float2(*reinterpret_cast<__half2*>(&r3.y));
            acc.x += w0 * a0.x; acc.y += w0 * a0.y; acc.z += w0 * b0.x; acc.w += w0 * b0.y;
            acc.x += w1 * a1.x; acc.y += w1 * a1.y; acc.z += w1 * b1.x; acc.w += w1 * b1.y;
            acc.x += w2 * a2.x; acc.y += w2 * a2.y; acc.z += w2 * b2.x; acc.w += w2 * b2.y;
            acc.x += w3 * a3.x; acc.y += w3 * a3.y; acc.z += w3 * b3.x; acc.w += w3 * b3.y;
        }
        for (; j < cnt; j++) {
            int   sj = __shfl_sync(0xffffffffu, sw.x, j);
            float wj = __int_as_float(__shfl_sync(0xffffffffu, sw.y, j));
            uint2 r = z2[sj * 32 + lane];
            float2 za = __half22float2(*reinterpret_cast<__half2*>(&r.x));
            float2 zb = __half22float2(*reinterpret_cast<__half2*>(&r.y));
            acc.x += wj * za.x; acc.y += wj * za.y;
            acc.z += wj * zb.x; acc.w += wj * zb.y;
        }
    }
    #pragma unroll
    for (int o = 16; o > 0; o >>= 1)
        den_l += __shfl_xor_sync(0xffffffffu, den_l, o);

    float inv = (end > start) ? (1.0f / den_l) : 0.f;
    acc.x *= inv; acc.y *= inv; acc.z *= inv; acc.w *= inv;
    *reinterpret_cast<float4*>(&out[n * D + lane * 4]) = acc;
}

// ---------------- launch ----------------
extern "C" void kernel_launch(void* const* d_in, const int* in_sizes, int n_in,
                              void* d_out, int out_size) {
    const float* h    = (const float*)d_in[0];
    const float* W    = (const float*)d_in[1];
    const float* attn = (const float*)d_in[2];
    const int* esrc   = (const int*)d_in[3];
    const int* edst   = (const int*)d_in[4];
    float* out        = (float*)d_out;

    (void)in_sizes; (void)n_in; (void)out_size;

    gemm_scores_kernel<<<(N_NODES + GBM - 1) / GBM, 256>>>(h, W, attn);
    zero_deg_kernel<<<(N_NODES + 255) / 256, 256>>>();
    hist_kernel<<<(N_EDGES / 4 + 255) / 256, 256>>>(edst);
    scan1_kernel<<<SCAN_BLKS, 1024>>>();
    scan2_kernel<<<1, 128>>>();
    scan3_kernel<<<(N_NODES + 255) / 256, 256>>>();
    scatter_kernel<<<(N_EDGES / 2 + 255) / 256, 256>>>(esrc, edst);
    aggregate_kernel<<<(N_NODES + 7) / 8, 256>>>(out);
}

// round 8
// speedup vs baseline: 1.1496x; 1.0668x over previous
#include <cuda_runtime.h>
#include <cuda_fp16.h>
#include <math.h>
#include <stdint.h>

#define N_NODES 100000
#define N_EDGES 1600000
#define D 128
#define NEG_SLOPE 0.01f
#define SCAN_BLKS ((N_NODES + 1023) / 1024)   // 98

// ---------------- scratch (no allocations allowed) ----------------
__device__ __half2 g_zh[N_NODES * (D / 2)];   // 25.6 MB, z in fp16
__device__ float g_ssrc[N_NODES];
__device__ float g_sdst[N_NODES];
__device__ int   g_deg[N_NODES];
__device__ int   g_off[N_NODES + 1];
__device__ int   g_cur[N_NODES];
__device__ int   g_csr_src[N_EDGES];
__device__ int   g_bsum[128];
__device__ int   g_boff[128];

// ---------------- GEMM z = h@W with fused scores (R5-proven scalar FFMA) ----------------
#define GBM 128
#define GBK 16
#define HT_STRIDE 132
#define SMEM_FLOATS 4352

__global__ __launch_bounds__(256) void gemm_scores_kernel(const float* __restrict__ h,
                                                          const float* __restrict__ W,
                                                          const float* __restrict__ attn) {
    __shared__ float smem[SMEM_FLOATS];
    float* hT = smem;                       // [GBK][HT_STRIDE]
    float* wS = smem + GBK * HT_STRIDE;     // [GBK][128]
    float* sp1 = smem;                      // [128][17] (reused)
    float* sp2 = smem + 128 * 17;

    const int t  = threadIdx.x;
    const int tx = t & 15;
    const int ty = t >> 4;
    const int row0 = blockIdx.x * GBM;

    float acc[8][8];
    #pragma unroll
    for (int i = 0; i < 8; i++)
        #pragma unroll
        for (int j = 0; j < 8; j++) acc[i][j] = 0.0f;

    for (int k0 = 0; k0 < D; k0 += GBK) {
        #pragma unroll
        for (int q = t; q < 512; q += 256) {
            int r  = q >> 2;
            int c4 = (q & 3) << 2;
            int grow = row0 + r;
            float4 v = make_float4(0.f, 0.f, 0.f, 0.f);
            if (grow < N_NODES)
                v = *reinterpret_cast<const float4*>(&h[grow * D + k0 + c4]);
            hT[(c4 + 0) * HT_STRIDE + r] = v.x;
            hT[(c4 + 1) * HT_STRIDE + r] = v.y;
            hT[(c4 + 2) * HT_STRIDE + r] = v.z;
            hT[(c4 + 3) * HT_STRIDE + r] = v.w;
        }
        #pragma unroll
        for (int q = t; q < 512; q += 256) {
            int r = q >> 5;
            int c = (q & 31) << 2;
            *reinterpret_cast<float4*>(&wS[r * D + c]) =
                *reinterpret_cast<const float4*>(&W[(k0 + r) * D + c]);
        }
        __syncthreads();

        #pragma unroll
        for (int kk = 0; kk < GBK; kk++) {
            float4 a0 = *reinterpret_cast<const float4*>(&hT[kk * HT_STRIDE + ty * 8]);
            float4 a1 = *reinterpret_cast<const float4*>(&hT[kk * HT_STRIDE + ty * 8 + 4]);
            float4 b0 = *reinterpret_cast<const float4*>(&wS[kk * D + tx * 8]);
            float4 b1 = *reinterpret_cast<const float4*>(&wS[kk * D + tx * 8 + 4]);
            float av[8] = {a0.x, a0.y, a0.z, a0.w, a1.x, a1.y, a1.z, a1.w};
            float bv[8] = {b0.x, b0.y, b0.z, b0.w, b1.x, b1.y, b1.z, b1.w};
            #pragma unroll
            for (int i = 0; i < 8; i++)
                #pragma unroll
                for (int j = 0; j < 8; j++)
                    acc[i][j] += av[i] * bv[j];
        }
        __syncthreads();
    }

    // write z as fp16
    #pragma unroll
    for (int i = 0; i < 8; i++) {
        int grow = row0 + ty * 8 + i;
        if (grow < N_NODES) {
            __half2 hv[4];
            #pragma unroll
            for (int j = 0; j < 4; j++)
                hv[j] = __floats2half2_rn(acc[i][2 * j], acc[i][2 * j + 1]);
            *reinterpret_cast<uint4*>(&g_zh[grow * (D / 2) + tx * 4]) =
                *reinterpret_cast<uint4*>(hv);
        }
    }

    // fused scores (fp32)
    float a1v[8], a2v[8];
    #pragma unroll
    for (int j = 0; j < 8; j++) {
        a1v[j] = attn[tx * 8 + j];
        a2v[j] = attn[D + tx * 8 + j];
    }
    float p1r[8], p2r[8];
    #pragma unroll
    for (int i = 0; i < 8; i++) {
        float p1 = 0.f, p2 = 0.f;
        #pragma unroll
        for (int j = 0; j < 8; j++) {
            p1 += acc[i][j] * a1v[j];
            p2 += acc[i][j] * a2v[j];
        }
        p1r[i] = p1; p2r[i] = p2;
    }
    __syncthreads();
    #pragma unroll
    for (int i = 0; i < 8; i++) {
        sp1[(ty * 8 + i) * 17 + tx] = p1r[i];
        sp2[(ty * 8 + i) * 17 + tx] = p2r[i];
    }
    __syncthreads();
    if (t < 128) {
        int grow = row0 + t;
        if (grow < N_NODES) {
            float s1 = 0.f, s2 = 0.f;
            #pragma unroll
            for (int k = 0; k < 16; k++) {
                s1 += sp1[t * 17 + k];
                s2 += sp2[t * 17 + k];
            }
            g_ssrc[grow] = s1;
            g_sdst[grow] = s2;
        }
    }
}

// ---------------- CSR build (R5-proven) ----------------
__global__ void zero_deg_kernel() {
    int i = blockIdx.x * blockDim.x + threadIdx.x;
    if (i < N_NODES) g_deg[i] = 0;
}

__global__ void hist_kernel(const int* __restrict__ dst) {
    int i = blockIdx.x * blockDim.x + threadIdx.x;
    if (i < N_EDGES) atomicAdd(&g_deg[dst[i]], 1);
}

__global__ __launch_bounds__(1024) void scan1_kernel() {
    __shared__ int wsum[32];
    int t = threadIdx.x, lane = t & 31, wid = t >> 5;
    int i = blockIdx.x * 1024 + t;
    int v = (i < N_NODES) ? g_deg[i] : 0;
    int x = v;
    #pragma unroll
    for (int o = 1; o < 32; o <<= 1) {
        int y = __shfl_up_sync(0xffffffffu, x, o);
        if (lane >= o) x += y;
    }
    if (lane == 31) wsum[wid] = x;
    __syncthreads();
    if (wid == 0) {
        int s = wsum[lane];
        #pragma unroll
        for (int o = 1; o < 32; o <<= 1) {
            int y = __shfl_up_sync(0xffffffffu, s, o);
            if (lane >= o) s += y;
        }
        wsum[lane] = s;
    }
    __syncthreads();
    int prefix = (wid > 0) ? wsum[wid - 1] : 0;
    int incl = x + prefix;
    if (i < N_NODES) g_off[i] = incl - v;
    if (t == 1023) g_bsum[blockIdx.x] = incl;
}

__global__ __launch_bounds__(128) void scan2_kernel() {
    __shared__ int wsum[4];
    int t = threadIdx.x, lane = t & 31, wid = t >> 5;
    int v = (t < SCAN_BLKS) ? g_bsum[t] : 0;
    int x = v;
    #pragma unroll
    for (int o = 1; o < 32; o <<= 1) {
        int y = __shfl_up_sync(0xffffffffu, x, o);
        if (lane >= o) x += y;
    }
    if (lane == 31) wsum[wid] = x;
    __syncthreads();
    int prefix = 0;
    for (int k = 0; k < wid; k++) prefix += wsum[k];
    int incl = x + prefix;
    if (t < SCAN_BLKS) g_boff[t] = incl - v;
}

__global__ void scan3_kernel() {
    int i = blockIdx.x * blockDim.x + threadIdx.x;
    if (i < N_NODES) {
        int v = g_off[i] + g_boff[i >> 10];
        g_off[i] = v;
        g_cur[i] = v;
    }
    if (i == 0) g_off[N_NODES] = N_EDGES;
}

__global__ void scatter_kernel(const int* __restrict__ src, const int* __restrict__ dst) {
    int i = blockIdx.x * blockDim.x + threadIdx.x;
    if (i < N_EDGES) {
        int d = dst[i];
        int p = atomicAdd(&g_cur[d], 1);
        g_csr_src[p] = src[i];
    }
}

// ---------------- single-pass aggregation: 2 edges/iter via LDG.128 ----------------
// Lanes 0-15 handle edge j, lanes 16-31 edge j+1. Each lane loads 16B (8 halves)
// of the edge's z-row; the two accumulator halves are summed via shfl_xor(16).
__global__ __launch_bounds__(256) void aggregate_kernel(float* __restrict__ out) {
    int wid  = threadIdx.x >> 5;
    int lane = threadIdx.x & 31;
    int n    = blockIdx.x * 8 + wid;
    if (n >= N_NODES) return;

    int start = g_off[n];
    int end   = g_off[n + 1];
    float sd  = g_sdst[n];

    const int half_sel = lane >> 4;       // 0: even edges, 1: odd edges
    const int colg     = lane & 15;       // 16B column group: halves [colg*8 .. colg*8+7]

    float accv[8];
    #pragma unroll
    for (int q = 0; q < 8; q++) accv[q] = 0.f;
    float den_l = 0.f;

    for (int base = start; base < end; base += 32) {
        int cnt = end - base;
        if (cnt > 32) cnt = 32;
        int s = 0; float w = 0.f;
        if (lane < cnt) {
            s = g_csr_src[base + lane];
            float e = g_ssrc[s] + sd;
            e = (e > 0.f) ? e : NEG_SLOPE * e;
            w = __expf(e);
            den_l += w;
        }
        #pragma unroll 4
        for (int j = 0; j < cnt; j += 2) {
            int idx = j + half_sel;                    // my edge within the batch
            int   sj = __shfl_sync(0xffffffffu, s, idx & 31);
            float wj = __shfl_sync(0xffffffffu, w, idx & 31);
            if (idx >= cnt) wj = 0.f;                  // odd-tail guard
            uint4 r = *reinterpret_cast<const uint4*>(&g_zh[sj * (D / 2) + colg * 4]);
            float2 z0 = __half22float2(*reinterpret_cast<__half2*>(&r.x));
            float2 z1 = __half22float2(*reinterpret_cast<__half2*>(&r.y));
            float2 z2 = __half22float2(*reinterpret_cast<__half2*>(&r.z));
            float2 z3 = __half22float2(*reinterpret_cast<__half2*>(&r.w));
            accv[0] += wj * z0.x; accv[1] += wj * z0.y;
            accv[2] += wj * z1.x; accv[3] += wj * z1.y;
            accv[4] += wj * z2.x; accv[5] += wj * z2.y;
            accv[6] += wj * z3.x; accv[7] += wj * z3.y;
        }
    }
    #pragma unroll
    for (int o = 16; o > 0; o >>= 1)
        den_l += __shfl_xor_sync(0xffffffffu, den_l, o);

    // combine the two edge-parity halves of the accumulator
    #pragma unroll
    for (int q = 0; q < 8; q++)
        accv[q] += __shfl_xor_sync(0xffffffffu, accv[q], 16);

    if (lane < 16) {
        float inv = (end > start) ? (1.0f / den_l) : 0.f;
        float4 o0 = make_float4(accv[0] * inv, accv[1] * inv, accv[2] * inv, accv[3] * inv);
        float4 o1 = make_float4(accv[4] * inv, accv[5] * inv, accv[6] * inv, accv[7] * inv);
        *reinterpret_cast<float4*>(&out[n * D + colg * 8])     = o0;
        *reinterpret_cast<float4*>(&out[n * D + colg * 8 + 4]) = o1;
    }
}

// ---------------- launch ----------------
extern "C" void kernel_launch(void* const* d_in, const int* in_sizes, int n_in,
                              void* d_out, int out_size) {
    const float* h    = (const float*)d_in[0];
    const float* W    = (const float*)d_in[1];
    const float* attn = (const float*)d_in[2];
    const int* esrc   = (const int*)d_in[3];
    const int* edst   = (const int*)d_in[4];
    float* out        = (float*)d_out;

    (void)in_sizes; (void)n_in; (void)out_size;

    gemm_scores_kernel<<<(N_NODES + GBM - 1) / GBM, 256>>>(h, W, attn);
    zero_deg_kernel<<<(N_NODES + 255) / 256, 256>>>();
    hist_kernel<<<(N_EDGES + 255) / 256, 256>>>(edst);
    scan1_kernel<<<SCAN_BLKS, 1024>>>();
    scan2_kernel<<<1, 128>>>();
    scan3_kernel<<<(N_NODES + 255) / 256, 256>>>();
    scatter_kernel<<<(N_EDGES + 255) / 256, 256>>>(esrc, edst);
    aggregate_kernel<<<(N_NODES + 7) / 8, 256>>>(out);
}

// round 14
// speedup vs baseline: 1.4722x; 1.2806x over previous
#include <cuda_runtime.h>
#include <cuda_fp16.h>
#include <math.h>
#include <stdint.h>

#define N_NODES 100000
#define N_EDGES 1600000
#define D 128
#define NEG_SLOPE 0.01f
#define SCAN_BLKS ((N_NODES + 1023) / 1024)   // 98

// ---------------- scratch (no allocations allowed) ----------------
__device__ __half2 g_zh[N_NODES * (D / 2)];   // 25.6 MB, z in fp16
__device__ float g_ssrc[N_NODES];
__device__ float g_sdst[N_NODES];
__device__ int   g_deg[N_NODES];
__device__ int   g_off[N_NODES + 1];
__device__ int   g_cur[N_NODES];
__device__ int   g_csr_src[N_EDGES];
__device__ int   g_bsum[128];
__device__ int   g_boff[128];

// pre-swizzled tf32 B tiles: [chunk][n*68 + k], n=0..127, k=0..63
#define KC 64
#define AST 68
__device__ __align__(16) uint32_t g_bt[2][128 * AST];

__device__ __forceinline__ uint32_t f2tf32(float f) {
    uint32_t u;
    asm("cvt.rna.tf32.f32 %0, %1;" : "=r"(u) : "f"(f));
    return u;
}

__device__ __forceinline__ void mma_tf32(float* c, const uint32_t* a,
                                         uint32_t b0, uint32_t b1) {
    asm volatile(
        "mma.sync.aligned.m16n8k8.row.col.f32.tf32.tf32.f32 "
        "{%0,%1,%2,%3}, {%4,%5,%6,%7}, {%8,%9}, {%0,%1,%2,%3};"
        : "+f"(c[0]), "+f"(c[1]), "+f"(c[2]), "+f"(c[3])
        : "r"(a[0]), "r"(a[1]), "r"(a[2]), "r"(a[3]), "r"(b0), "r"(b1));
}

// ---------------- prep: W -> tf32, transposed, padded layout ----------------
__global__ void prep_b_kernel(const float* __restrict__ W) {
    int idx = blockIdx.x * 256 + threadIdx.x;   // 0..16383, idx = kg*128 + n
    if (idx < 16384) {
        int kg = idx >> 7, n = idx & 127;
        g_bt[kg >> 6][n * AST + (kg & 63)] = f2tf32(W[kg * 128 + n]);
    }
}

// ---------------- tf32 mma.sync GEMM: z = h@W, fused scores ----------------
// CTA: 128 rows x 128 cols x K=128 (two 64-chunks). 8 warps, each 32x64.
#define GEMM_SMEM (2 * 128 * AST * 4)   // 69632 B

__global__ __launch_bounds__(256) void gemm_mma_kernel(const float* __restrict__ h,
                                                       const float* __restrict__ attn) {
    extern __shared__ __align__(16) uint32_t smem[];
    uint32_t* As = smem;                  // [128][AST]
    uint32_t* Bs = smem + 128 * AST;      // [128][AST]
    float* sp1 = reinterpret_cast<float*>(smem);          // reused post-mma
    float* sp2 = reinterpret_cast<float*>(smem) + 1152;

    const int t = threadIdx.x;
    const int wid = t >> 5, lane = t & 31;
    const int g = lane >> 2, q = lane & 3;
    const int wr = wid >> 1, wc = wid & 1;
    const int row0 = blockIdx.x * 128;

    float c[2][8][4];
    #pragma unroll
    for (int i = 0; i < 2; i++)
        #pragma unroll
        for (int j = 0; j < 8; j++)
            #pragma unroll
            for (int u = 0; u < 4; u++) c[i][j][u] = 0.f;

    for (int ch = 0; ch < 2; ch++) {
        // A: h rows -> tf32, [r][k] stride AST
        #pragma unroll
        for (int p = t; p < 2048; p += 256) {
            int r = p >> 4, c4 = (p & 15) << 2;
            int grow = row0 + r;
            float4 v = make_float4(0.f, 0.f, 0.f, 0.f);
            if (grow < N_NODES)
                v = *reinterpret_cast<const float4*>(&h[grow * D + ch * KC + c4]);
            uint4 u = make_uint4(f2tf32(v.x), f2tf32(v.y), f2tf32(v.z), f2tf32(v.w));
            *reinterpret_cast<uint4*>(&As[r * AST + c4]) = u;
        }
        // B: linear copy of prepped tile (2176 uint4)
        {
            const uint4* srcB = reinterpret_cast<const uint4*>(g_bt[ch]);
            uint4* dstB = reinterpret_cast<uint4*>(Bs);
            for (int p = t; p < 2176; p += 256) dstB[p] = srcB[p];
        }
        __syncthreads();

        #pragma unroll
        for (int ks = 0; ks < 8; ks++) {
            uint32_t a[2][4];
            #pragma unroll
            for (int i = 0; i < 2; i++) {
                int r = wr * 32 + i * 16 + g;
                a[i][0] = As[r * AST + ks * 8 + q];
                a[i][1] = As[(r + 8) * AST + ks * 8 + q];
                a[i][2] = As[r * AST + ks * 8 + q + 4];
                a[i][3] = As[(r + 8) * AST + ks * 8 + q + 4];
            }
            #pragma unroll
            for (int j = 0; j < 8; j++) {
                int n = wc * 64 + j * 8 + g;
                uint32_t b0 = Bs[n * AST + ks * 8 + q];
                uint32_t b1 = Bs[n * AST + ks * 8 + q + 4];
                mma_tf32(c[0][j], a[0], b0, b1);
                mma_tf32(c[1][j], a[1], b0, b1);
            }
        }
        __syncthreads();
    }

    // epilogue: z (fp16) stores + fused score partials
    #pragma unroll
    for (int i = 0; i < 2; i++) {
        int rA = wr * 32 + i * 16 + g;
        int rB = rA + 8;
        int growA = row0 + rA, growB = row0 + rB;
        float p1a = 0.f, p1b = 0.f, p2a = 0.f, p2b = 0.f;
        #pragma unroll
        for (int j = 0; j < 8; j++) {
            int col = wc * 64 + j * 8 + 2 * q;
            float a1c0 = attn[col], a1c1 = attn[col + 1];
            float a2c0 = attn[D + col], a2c1 = attn[D + col + 1];
            p1a += c[i][j][0] * a1c0 + c[i][j][1] * a1c1;
            p2a += c[i][j][0] * a2c0 + c[i][j][1] * a2c1;
            p1b += c[i][j][2] * a1c0 + c[i][j][3] * a1c1;
            p2b += c[i][j][2] * a2c0 + c[i][j][3] * a2c1;
            if (growA < N_NODES)
                g_zh[growA * 64 + (col >> 1)] = __floats2half2_rn(c[i][j][0], c[i][j][1]);
            if (growB < N_NODES)
                g_zh[growB * 64 + (col >> 1)] = __floats2half2_rn(c[i][j][2], c[i][j][3]);
        }
        sp1[rA * 8 + wc * 4 + q] = p1a;
        sp1[rB * 8 + wc * 4 + q] = p1b;
        sp2[rA * 8 + wc * 4 + q] = p2a;
        sp2[rB * 8 + wc * 4 + q] = p2b;
    }
    __syncthreads();
    if (t < 128) {
        int grow = row0 + t;
        if (grow < N_NODES) {
            float s1 = 0.f, s2 = 0.f;
            #pragma unroll
            for (int k = 0; k < 8; k++) {
                s1 += sp1[t * 8 + k];
                s2 += sp2[t * 8 + k];
            }
            g_ssrc[grow] = s1;
            g_sdst[grow] = s2;
        }
    }
}

// ---------------- CSR build (R5-proven) ----------------
__global__ void zero_deg_kernel() {
    int i = blockIdx.x * blockDim.x + threadIdx.x;
    if (i < N_NODES) g_deg[i] = 0;
}

__global__ void hist_kernel(const int* __restrict__ dst) {
    int i = blockIdx.x * blockDim.x + threadIdx.x;
    if (i < N_EDGES) atomicAdd(&g_deg[dst[i]], 1);
}

__global__ __launch_bounds__(1024) void scan1_kernel() {
    __shared__ int wsum[32];
    int t = threadIdx.x, lane = t & 31, wid = t >> 5;
    int i = blockIdx.x * 1024 + t;
    int v = (i < N_NODES) ? g_deg[i] : 0;
    int x = v;
    #pragma unroll
    for (int o = 1; o < 32; o <<= 1) {
        int y = __shfl_up_sync(0xffffffffu, x, o);
        if (lane >= o) x += y;
    }
    if (lane == 31) wsum[wid] = x;
    __syncthreads();
    if (wid == 0) {
        int s = wsum[lane];
        #pragma unroll
        for (int o = 1; o < 32; o <<= 1) {
            int y = __shfl_up_sync(0xffffffffu, s, o);
            if (lane >= o) s += y;
        }
        wsum[lane] = s;
    }
    __syncthreads();
    int prefix = (wid > 0) ? wsum[wid - 1] : 0;
    int incl = x + prefix;
    if (i < N_NODES) g_off[i] = incl - v;
    if (t == 1023) g_bsum[blockIdx.x] = incl;
}

__global__ __launch_bounds__(128) void scan2_kernel() {
    __shared__ int wsum[4];
    int t = threadIdx.x, lane = t & 31, wid = t >> 5;
    int v = (t < SCAN_BLKS) ? g_bsum[t] : 0;
    int x = v;
    #pragma unroll
    for (int o = 1; o < 32; o <<= 1) {
        int y = __shfl_up_sync(0xffffffffu, x, o);
        if (lane >= o) x += y;
    }
    if (lane == 31) wsum[wid] = x;
    __syncthreads();
    int prefix = 0;
    for (int k = 0; k < wid; k++) prefix += wsum[k];
    int incl = x + prefix;
    if (t < SCAN_BLKS) g_boff[t] = incl - v;
}

__global__ void scan3_kernel() {
    int i = blockIdx.x * blockDim.x + threadIdx.x;
    if (i < N_NODES) {
        int v = g_off[i] + g_boff[i >> 10];
        g_off[i] = v;
        g_cur[i] = v;
    }
    if (i == 0) g_off[N_NODES] = N_EDGES;
}

__global__ void scatter_kernel(const int* __restrict__ src, const int* __restrict__ dst) {
    int i = blockIdx.x * blockDim.x + threadIdx.x;
    if (i < N_EDGES) {
        int d = dst[i];
        int p = atomicAdd(&g_cur[d], 1);
        g_csr_src[p] = src[i];
    }
}

// ---------------- single-pass aggregation (R5-proven) ----------------
__global__ __launch_bounds__(256) void aggregate_kernel(float* __restrict__ out) {
    int wid  = threadIdx.x >> 5;
    int lane = threadIdx.x & 31;
    int n    = blockIdx.x * 8 + wid;
    if (n >= N_NODES) return;

    int start = g_off[n];
    int end   = g_off[n + 1];
    float sd  = g_sdst[n];

    float4 acc = make_float4(0.f, 0.f, 0.f, 0.f);
    float den_l = 0.f;
    const int h2col = lane * 2;

    for (int base = start; base < end; base += 32) {
        int cnt = end - base;
        if (cnt > 32) cnt = 32;
        int s = 0; float w = 0.f;
        if (lane < cnt) {
            s = g_csr_src[base + lane];
            float e = g_ssrc[s] + sd;
            e = (e > 0.f) ? e : NEG_SLOPE * e;
            w = __expf(e);
            den_l += w;
        }
        #pragma unroll 4
        for (int j = 0; j < cnt; j++) {
            int   sj = __shfl_sync(0xffffffffu, s, j);
            float wj = __shfl_sync(0xffffffffu, w, j);
            uint2 raw = *reinterpret_cast<const uint2*>(&g_zh[sj * (D / 2) + h2col]);
            float2 z0 = __half22float2(*reinterpret_cast<__half2*>(&raw.x));
            float2 z1 = __half22float2(*reinterpret_cast<__half2*>(&raw.y));
            acc.x += wj * z0.x;
            acc.y += wj * z0.y;
            acc.z += wj * z1.x;
            acc.w += wj * z1.y;
        }
    }
    #pragma unroll
    for (int o = 16; o > 0; o >>= 1)
        den_l += __shfl_xor_sync(0xffffffffu, den_l, o);

    float inv = (end > start) ? (1.0f / den_l) : 0.f;
    acc.x *= inv; acc.y *= inv; acc.z *= inv; acc.w *= inv;
    *reinterpret_cast<float4*>(&out[n * D + lane * 4]) = acc;
}

// ---------------- launch ----------------
extern "C" void kernel_launch(void* const* d_in, const int* in_sizes, int n_in,
                              void* d_out, int out_size) {
    const float* h    = (const float*)d_in[0];
    const float* W    = (const float*)d_in[1];
    const float* attn = (const float*)d_in[2];
    const int* esrc   = (const int*)d_in[3];
    const int* edst   = (const int*)d_in[4];
    float* out        = (float*)d_out;

    (void)in_sizes; (void)n_in; (void)out_size;

    cudaFuncSetAttribute(gemm_mma_kernel,
                         cudaFuncAttributeMaxDynamicSharedMemorySize, GEMM_SMEM);

    prep_b_kernel<<<64, 256>>>(W);
    gemm_mma_kernel<<<(N_NODES + 127) / 128, 256, GEMM_SMEM>>>(h, attn);
    zero_deg_kernel<<<(N_NODES + 255) / 256, 256>>>();
    hist_kernel<<<(N_EDGES + 255) / 256, 256>>>(edst);
    scan1_kernel<<<SCAN_BLKS, 1024>>>();
    scan2_kernel<<<1, 128>>>();
    scan3_kernel<<<(N_NODES + 255) / 256, 256>>>();
    scatter_kernel<<<(N_EDGES + 255) / 256, 256>>>(esrc, edst);
    aggregate_kernel<<<(N_NODES + 7) / 8, 256>>>(out);
}

// round 16
// speedup vs baseline: 1.5653x; 1.0633x over previous
#include <cuda_runtime.h>
#include <cuda_fp16.h>
#include <math.h>
#include <stdint.h>

#define N_NODES 100000
#define N_EDGES 1600000
#define D 128
#define NEG_SLOPE 0.01f
#define SCAN_BLKS ((N_NODES + 1023) / 1024)   // 98

// ---------------- scratch (no allocations allowed) ----------------
__device__ __half2 g_zh[N_NODES * (D / 2)];   // 25.6 MB, z in fp16
__device__ float g_ssrc[N_NODES];
__device__ float g_sdst[N_NODES];
__device__ int   g_deg[N_NODES];
__device__ int   g_off[N_NODES + 1];
__device__ int   g_cur[N_NODES];
__device__ int   g_csr_src[N_EDGES];
__device__ int   g_bsum[128];
__device__ int   g_boff[128];

// pre-swizzled tf32 B tiles: [chunk][n*68 + k], n=0..127, k=0..63
#define KC 64
#define AST 68
__device__ __align__(16) uint32_t g_bt[2][128 * AST];

__device__ __forceinline__ uint32_t f2tf32(float f) {
    uint32_t u;
    asm("cvt.rna.tf32.f32 %0, %1;" : "=r"(u) : "f"(f));
    return u;
}

__device__ __forceinline__ void mma_tf32(float* c, const uint32_t* a,
                                         uint32_t b0, uint32_t b1) {
    asm volatile(
        "mma.sync.aligned.m16n8k8.row.col.f32.tf32.tf32.f32 "
        "{%0,%1,%2,%3}, {%4,%5,%6,%7}, {%8,%9}, {%0,%1,%2,%3};"
        : "+f"(c[0]), "+f"(c[1]), "+f"(c[2]), "+f"(c[3])
        : "r"(a[0]), "r"(a[1]), "r"(a[2]), "r"(a[3]), "r"(b0), "r"(b1));
}

// ---------------- prep: W -> tf32, transposed, padded layout ----------------
__global__ void prep_b_kernel(const float* __restrict__ W) {
    int idx = blockIdx.x * 256 + threadIdx.x;   // 0..16383, idx = kg*128 + n
    if (idx < 16384) {
        int kg = idx >> 7, n = idx & 127;
        g_bt[kg >> 6][n * AST + (kg & 63)] = f2tf32(W[kg * 128 + n]);
    }
}

// ---------------- tf32 mma.sync GEMM: z = h@W, fused scores ----------------
// CTA: 128 rows x 128 cols x K=128 (two 64-chunks). 8 warps, each 32x64.
#define GEMM_SMEM (2 * 128 * AST * 4)   // 69632 B

__global__ __launch_bounds__(256) void gemm_mma_kernel(const float* __restrict__ h,
                                                       const float* __restrict__ attn) {
    extern __shared__ __align__(16) uint32_t smem[];
    uint32_t* As = smem;                  // [128][AST]
    uint32_t* Bs = smem + 128 * AST;      // [128][AST]
    float* sp1 = reinterpret_cast<float*>(smem);          // reused post-mma
    float* sp2 = reinterpret_cast<float*>(smem) + 1152;

    const int t = threadIdx.x;
    const int wid = t >> 5, lane = t & 31;
    const int g = lane >> 2, q = lane & 3;
    const int wr = wid >> 1, wc = wid & 1;
    const int row0 = blockIdx.x * 128;

    float c[2][8][4];
    #pragma unroll
    for (int i = 0; i < 2; i++)
        #pragma unroll
        for (int j = 0; j < 8; j++)
            #pragma unroll
            for (int u = 0; u < 4; u++) c[i][j][u] = 0.f;

    for (int ch = 0; ch < 2; ch++) {
        // A: h rows -> tf32, [r][k] stride AST
        #pragma unroll
        for (int p = t; p < 2048; p += 256) {
            int r = p >> 4, c4 = (p & 15) << 2;
            int grow = row0 + r;
            float4 v = make_float4(0.f, 0.f, 0.f, 0.f);
            if (grow < N_NODES)
                v = *reinterpret_cast<const float4*>(&h[grow * D + ch * KC + c4]);
            uint4 u = make_uint4(f2tf32(v.x), f2tf32(v.y), f2tf32(v.z), f2tf32(v.w));
            *reinterpret_cast<uint4*>(&As[r * AST + c4]) = u;
        }
        // B: linear copy of prepped tile (2176 uint4)
        {
            const uint4* srcB = reinterpret_cast<const uint4*>(g_bt[ch]);
            uint4* dstB = reinterpret_cast<uint4*>(Bs);
            for (int p = t; p < 2176; p += 256) dstB[p] = srcB[p];
        }
        __syncthreads();

        #pragma unroll
        for (int ks = 0; ks < 8; ks++) {
            uint32_t a[2][4];
            #pragma unroll
            for (int i = 0; i < 2; i++) {
                int r = wr * 32 + i * 16 + g;
                a[i][0] = As[r * AST + ks * 8 + q];
                a[i][1] = As[(r + 8) * AST + ks * 8 + q];
                a[i][2] = As[r * AST + ks * 8 + q + 4];
                a[i][3] = As[(r + 8) * AST + ks * 8 + q + 4];
            }
            #pragma unroll
            for (int j = 0; j < 8; j++) {
                int n = wc * 64 + j * 8 + g;
                uint32_t b0 = Bs[n * AST + ks * 8 + q];
                uint32_t b1 = Bs[n * AST + ks * 8 + q + 4];
                mma_tf32(c[0][j], a[0], b0, b1);
                mma_tf32(c[1][j], a[1], b0, b1);
            }
        }
        __syncthreads();
    }

    // epilogue: z (fp16) stores + fused score partials
    #pragma unroll
    for (int i = 0; i < 2; i++) {
        int rA = wr * 32 + i * 16 + g;
        int rB = rA + 8;
        int growA = row0 + rA, growB = row0 + rB;
        float p1a = 0.f, p1b = 0.f, p2a = 0.f, p2b = 0.f;
        #pragma unroll
        for (int j = 0; j < 8; j++) {
            int col = wc * 64 + j * 8 + 2 * q;
            float a1c0 = attn[col], a1c1 = attn[col + 1];
            float a2c0 = attn[D + col], a2c1 = attn[D + col + 1];
            p1a += c[i][j][0] * a1c0 + c[i][j][1] * a1c1;
            p2a += c[i][j][0] * a2c0 + c[i][j][1] * a2c1;
            p1b += c[i][j][2] * a1c0 + c[i][j][3] * a1c1;
            p2b += c[i][j][2] * a2c0 + c[i][j][3] * a2c1;
            if (growA < N_NODES)
                g_zh[growA * 64 + (col >> 1)] = __floats2half2_rn(c[i][j][0], c[i][j][1]);
            if (growB < N_NODES)
                g_zh[growB * 64 + (col >> 1)] = __floats2half2_rn(c[i][j][2], c[i][j][3]);
        }
        sp1[rA * 8 + wc * 4 + q] = p1a;
        sp1[rB * 8 + wc * 4 + q] = p1b;
        sp2[rA * 8 + wc * 4 + q] = p2a;
        sp2[rB * 8 + wc * 4 + q] = p2b;
    }
    __syncthreads();
    if (t < 128) {
        int grow = row0 + t;
        if (grow < N_NODES) {
            float s1 = 0.f, s2 = 0.f;
            #pragma unroll
            for (int k = 0; k < 8; k++) {
                s1 += sp1[t * 8 + k];
                s2 += sp2[t * 8 + k];
            }
            g_ssrc[grow] = s1;
            g_sdst[grow] = s2;
        }
    }
}

// ---------------- CSR build (R5-proven) ----------------
__global__ void zero_deg_kernel() {
    int i = blockIdx.x * blockDim.x + threadIdx.x;
    if (i < N_NODES) g_deg[i] = 0;
}

__global__ void hist_kernel(const int* __restrict__ dst) {
    int i = blockIdx.x * blockDim.x + threadIdx.x;
    if (i < N_EDGES) atomicAdd(&g_deg[dst[i]], 1);
}

__global__ __launch_bounds__(1024) void scan1_kernel() {
    __shared__ int wsum[32];
    int t = threadIdx.x, lane = t & 31, wid = t >> 5;
    int i = blockIdx.x * 1024 + t;
    int v = (i < N_NODES) ? g_deg[i] : 0;
    int x = v;
    #pragma unroll
    for (int o = 1; o < 32; o <<= 1) {
        int y = __shfl_up_sync(0xffffffffu, x, o);
        if (lane >= o) x += y;
    }
    if (lane == 31) wsum[wid] = x;
    __syncthreads();
    if (wid == 0) {
        int s = wsum[lane];
        #pragma unroll
        for (int o = 1; o < 32; o <<= 1) {
            int y = __shfl_up_sync(0xffffffffu, s, o);
            if (lane >= o) s += y;
        }
        wsum[lane] = s;
    }
    __syncthreads();
    int prefix = (wid > 0) ? wsum[wid - 1] : 0;
    int incl = x + prefix;
    if (i < N_NODES) g_off[i] = incl - v;
    if (t == 1023) g_bsum[blockIdx.x] = incl;
}

__global__ __launch_bounds__(128) void scan2_kernel() {
    __shared__ int wsum[4];
    int t = threadIdx.x, lane = t & 31, wid = t >> 5;
    int v = (t < SCAN_BLKS) ? g_bsum[t] : 0;
    int x = v;
    #pragma unroll
    for (int o = 1; o < 32; o <<= 1) {
        int y = __shfl_up_sync(0xffffffffu, x, o);
        if (lane >= o) x += y;
    }
    if (lane == 31) wsum[wid] = x;
    __syncthreads();
    int prefix = 0;
    for (int k = 0; k < wid; k++) prefix += wsum[k];
    int incl = x + prefix;
    if (t < SCAN_BLKS) g_boff[t] = incl - v;
}

__global__ void scan3_kernel() {
    int i = blockIdx.x * blockDim.x + threadIdx.x;
    if (i < N_NODES) {
        int v = g_off[i] + g_boff[i >> 10];
        g_off[i] = v;
        g_cur[i] = v;
    }
    if (i == 0) g_off[N_NODES] = N_EDGES;
}

__global__ void scatter_kernel(const int* __restrict__ src, const int* __restrict__ dst) {
    int i = blockIdx.x * blockDim.x + threadIdx.x;
    if (i < N_EDGES) {
        int d = dst[i];
        int p = atomicAdd(&g_cur[d], 1);
        g_csr_src[p] = src[i];
    }
}

// ---------------- single-pass aggregation (R5-proven) ----------------
__global__ __launch_bounds__(256) void aggregate_kernel(float* __restrict__ out) {
    int wid  = threadIdx.x >> 5;
    int lane = threadIdx.x & 31;
    int n    = blockIdx.x * 8 + wid;
    if (n >= N_NODES) return;

    int start = g_off[n];
    int end   = g_off[n + 1];
    float sd  = g_sdst[n];

    float4 acc = make_float4(0.f, 0.f, 0.f, 0.f);
    float den_l = 0.f;
    const int h2col = lane * 2;

    for (int base = start; base < end; base += 32) {
        int cnt = end - base;
        if (cnt > 32) cnt = 32;
        int s = 0; float w = 0.f;
        if (lane < cnt) {
            s = g_csr_src[base + lane];
            float e = g_ssrc[s] + sd;
            e = (e > 0.f) ? e : NEG_SLOPE * e;
            w = __expf(e);
            den_l += w;
        }
        #pragma unroll 4
        for (int j = 0; j < cnt; j++) {
            int   sj = __shfl_sync(0xffffffffu, s, j);
            float wj = __shfl_sync(0xffffffffu, w, j);
            uint2 raw = *reinterpret_cast<const uint2*>(&g_zh[sj * (D / 2) + h2col]);
            float2 z0 = __half22float2(*reinterpret_cast<__half2*>(&raw.x));
            float2 z1 = __half22float2(*reinterpret_cast<__half2*>(&raw.y));
            acc.x += wj * z0.x;
            acc.y += wj * z0.y;
            acc.z += wj * z1.x;
            acc.w += wj * z1.y;
        }
    }
    #pragma unroll
    for (int o = 16; o > 0; o >>= 1)
        den_l += __shfl_xor_sync(0xffffffffu, den_l, o);

    float inv = (end > start) ? (1.0f / den_l) : 0.f;
    acc.x *= inv; acc.y *= inv; acc.z *= inv; acc.w *= inv;
    *reinterpret_cast<float4*>(&out[n * D + lane * 4]) = acc;
}

// ---------------- launch: fork CSR chain and GEMM chain onto parallel streams ----------------
extern "C" void kernel_launch(void* const* d_in, const int* in_sizes, int n_in,
                              void* d_out, int out_size) {
    const float* h    = (const float*)d_in[0];
    const float* W    = (const float*)d_in[1];
    const float* attn = (const float*)d_in[2];
    const int* esrc   = (const int*)d_in[3];
    const int* edst   = (const int*)d_in[4];
    float* out        = (float*)d_out;

    (void)in_sizes; (void)n_in; (void)out_size;

    cudaFuncSetAttribute(gemm_mma_kernel,
                         cudaFuncAttributeMaxDynamicSharedMemorySize, GEMM_SMEM);

    cudaStream_t s2;
    cudaStreamCreateWithFlags(&s2, cudaStreamNonBlocking);
    cudaEvent_t eFork, eJoin;
    cudaEventCreateWithFlags(&eFork, cudaEventDisableTiming);
    cudaEventCreateWithFlags(&eJoin, cudaEventDisableTiming);

    // fork: s2 branches off the origin (capture) stream
    cudaEventRecord(eFork, 0);
    cudaStreamWaitEvent(s2, eFork, 0);

    // branch A (origin stream): GEMM chain — z, scores
    prep_b_kernel<<<64, 256>>>(W);
    gemm_mma_kernel<<<(N_NODES + 127) / 128, 256, GEMM_SMEM>>>(h, attn);

    // branch B (s2): CSR build — independent of z/scores
    zero_deg_kernel<<<(N_NODES + 255) / 256, 256, 0, s2>>>();
    hist_kernel<<<(N_EDGES + 255) / 256, 256, 0, s2>>>(edst);
    scan1_kernel<<<SCAN_BLKS, 1024, 0, s2>>>();
    scan2_kernel<<<1, 128, 0, s2>>>();
    scan3_kernel<<<(N_NODES + 255) / 256, 256, 0, s2>>>();
    scatter_kernel<<<(N_EDGES + 255) / 256, 256, 0, s2>>>(esrc, edst);

    // join: origin stream waits for CSR branch, then aggregates
    cudaEventRecord(eJoin, s2);
    cudaStreamWaitEvent(0, eJoin, 0);
    aggregate_kernel<<<(N_NODES + 7) / 8, 256>>>(out);

    // (handles intentionally not destroyed while capture may be active;
    //  kernel_launch is invoked only a handful of times, no device memory involved)
}